// round 1
// baseline (speedup 1.0000x reference)
#include <cuda_runtime.h>
#include <cuda_bf16.h>

#define CIN   64
#define COUT  64
#define WARPS 8
#define PAIRS 8           // pairs per warp per iteration
#define PAIRS_PER_BLOCK (WARPS * PAIRS)   // 64
#define BN_EPS 1e-5f

// ---------------------------------------------------------------------------
// Zero the output accumulator (d_out is poisoned to 0xAA by the harness).
// ---------------------------------------------------------------------------
__global__ void __launch_bounds__(256) zero_kernel(float4* __restrict__ out, int n4) {
    int i = blockIdx.x * blockDim.x + threadIdx.x;
    if (i < n4) out[i] = make_float4(0.f, 0.f, 0.f, 0.f);
}

// ---------------------------------------------------------------------------
// Main gather-GEMM-scatter kernel.
// grid = (chunks, K). Each block: stage W[k] (64x64 fp32) in smem, then each
// warp processes 8 pairs/iter: gather 8 feat rows to smem, dense 64x64 matvec
// with 2 output channels per lane, scatter via vector f32 atomics.
// ---------------------------------------------------------------------------
__global__ void __launch_bounds__(256) spconv_kernel(
    const float* __restrict__ feats,
    const float* __restrict__ W,
    const int*   __restrict__ in_idx,
    const int*   __restrict__ out_idx,
    float*       __restrict__ out,
    int M)
{
    const int k    = blockIdx.y;
    const int warp = threadIdx.x >> 5;
    const int lane = threadIdx.x & 31;

    __shared__ float Wsm[CIN * COUT];                 // 16 KB
    __shared__ float Fsm[WARPS][PAIRS][CIN];          // 16 KB

    // Stage W[k] (row-major: Wsm[ci*64 + co])
    {
        const float4* Wg  = (const float4*)(W + (size_t)k * CIN * COUT);
        float4*       Ws4 = (float4*)Wsm;
        #pragma unroll
        for (int i = threadIdx.x; i < CIN * COUT / 4; i += 256)
            Ws4[i] = Wg[i];
    }
    __syncthreads();

    const int* inK  = in_idx  + (size_t)k * M;
    const int* outK = out_idx + (size_t)k * M;
    const float2* W2 = (const float2*)Wsm;   // W2[ci*32 + lane] = channels (2*lane, 2*lane+1)

    for (int base = blockIdx.x * PAIRS_PER_BLOCK; base < M;
         base += gridDim.x * PAIRS_PER_BLOCK) {

        const int gp0 = base + warp * PAIRS;

        // ---- Gather 8 feat rows (256B each) into this warp's smem buffer.
        // Two rows per step: lanes 0-15 -> row p, lanes 16-31 -> row p+1.
        #pragma unroll
        for (int r = 0; r < PAIRS / 2; r++) {
            int p   = r * 2 + (lane >> 4);
            int gp  = gp0 + p;
            int idx = (gp < M) ? inK[gp] : 0;
            const float4* src = (const float4*)(feats + (size_t)idx * CIN);
            int c4 = lane & 15;
            ((float4*)Fsm[warp][p])[c4] = src[c4];
        }
        __syncwarp();

        // ---- Dense 64x64 matvec for 8 pairs; lane owns channels 2*lane, 2*lane+1.
        float2 acc[PAIRS];
        #pragma unroll
        for (int p = 0; p < PAIRS; p++) acc[p] = make_float2(0.f, 0.f);

        #pragma unroll
        for (int ci = 0; ci < CIN; ci += 4) {
            float2 w0 = W2[(ci + 0) * 32 + lane];
            float2 w1 = W2[(ci + 1) * 32 + lane];
            float2 w2 = W2[(ci + 2) * 32 + lane];
            float2 w3 = W2[(ci + 3) * 32 + lane];
            #pragma unroll
            for (int p = 0; p < PAIRS; p++) {
                float4 f = *(const float4*)&Fsm[warp][p][ci];   // broadcast
                acc[p].x = fmaf(f.x, w0.x, acc[p].x);
                acc[p].y = fmaf(f.x, w0.y, acc[p].y);
                acc[p].x = fmaf(f.y, w1.x, acc[p].x);
                acc[p].y = fmaf(f.y, w1.y, acc[p].y);
                acc[p].x = fmaf(f.z, w2.x, acc[p].x);
                acc[p].y = fmaf(f.z, w2.y, acc[p].y);
                acc[p].x = fmaf(f.w, w3.x, acc[p].x);
                acc[p].y = fmaf(f.w, w3.y, acc[p].y);
            }
        }

        // ---- Scatter: one vector f32 atomic per lane per pair.
        #pragma unroll
        for (int p = 0; p < PAIRS; p++) {
            int gp = gp0 + p;
            if (gp < M) {
                int o = outK[gp];                          // warp-uniform
                float* dst = out + (size_t)o * COUT + 2 * lane;
                asm volatile("red.global.add.v2.f32 [%0], {%1, %2};"
                             :: "l"(dst), "f"(acc[p].x), "f"(acc[p].y)
                             : "memory");
            }
        }
        __syncwarp();   // all reads of Fsm done before next iteration rewrites it
    }
}

// ---------------------------------------------------------------------------
// BatchNorm (inference) + ReLU, in place on the accumulated output.
// ---------------------------------------------------------------------------
__global__ void __launch_bounds__(256) bn_relu_kernel(
    float4* __restrict__ out,
    const float* __restrict__ gamma,
    const float* __restrict__ beta,
    const float* __restrict__ rmean,
    const float* __restrict__ rvar,
    int total4)
{
    int i = blockIdx.x * blockDim.x + threadIdx.x;
    if (i >= total4) return;
    int c = (i & (COUT / 4 - 1)) * 4;   // channel base for this float4

    float4 v = out[i];
    float s0 = rsqrtf(rvar[c + 0] + BN_EPS) * gamma[c + 0];
    float s1 = rsqrtf(rvar[c + 1] + BN_EPS) * gamma[c + 1];
    float s2 = rsqrtf(rvar[c + 2] + BN_EPS) * gamma[c + 2];
    float s3 = rsqrtf(rvar[c + 3] + BN_EPS) * gamma[c + 3];

    v.x = fmaf(v.x - rmean[c + 0], s0, beta[c + 0]);
    v.y = fmaf(v.y - rmean[c + 1], s1, beta[c + 1]);
    v.z = fmaf(v.z - rmean[c + 2], s2, beta[c + 2]);
    v.w = fmaf(v.w - rmean[c + 3], s3, beta[c + 3]);

    v.x = fmaxf(v.x, 0.f);
    v.y = fmaxf(v.y, 0.f);
    v.z = fmaxf(v.z, 0.f);
    v.w = fmaxf(v.w, 0.f);
    out[i] = v;
}

// ---------------------------------------------------------------------------
extern "C" void kernel_launch(void* const* d_in, const int* in_sizes, int n_in,
                              void* d_out, int out_size)
{
    const float* feats   = (const float*)d_in[0];
    const float* W       = (const float*)d_in[1];
    const float* gamma   = (const float*)d_in[2];
    const float* beta    = (const float*)d_in[3];
    const float* rmean   = (const float*)d_in[4];
    const float* rvar    = (const float*)d_in[5];
    const int*   in_idx  = (const int*)d_in[6];
    const int*   out_idx = (const int*)d_in[7];
    float*       out     = (float*)d_out;

    const int N = in_sizes[0] / CIN;
    const int K = in_sizes[1] / (CIN * COUT);
    const int M = in_sizes[6] / K;

    // 1) zero accumulator
    int n4 = N * COUT / 4;
    zero_kernel<<<(n4 + 255) / 256, 256>>>((float4*)out, n4);

    // 2) gather-GEMM-scatter; ~512 pairs per block -> good W-staging amortization
    int chunks = (M + PAIRS_PER_BLOCK * 8 - 1) / (PAIRS_PER_BLOCK * 8);
    if (chunks < 1) chunks = 1;
    dim3 grid(chunks, K);
    spconv_kernel<<<grid, 256>>>(feats, W, in_idx, out_idx, out, M);

    // 3) BN + ReLU in place
    int total4 = N * COUT / 4;
    bn_relu_kernel<<<(total4 + 255) / 256, 256>>>((float4*)out, gamma, beta,
                                                  rmean, rvar, total4);
}

// round 3
// speedup vs baseline: 1.4231x; 1.4231x over previous
#include <cuda_runtime.h>
#include <cuda_bf16.h>
#include <cstdint>

#define CIN    64
#define COUT   64
#define TILE_M 128
#define BN_EPS 1e-5f
#define STRIDE 68                    // smem row stride in floats (bank-conflict-free)

// smem layout (in floats)
#define SM_W 0                       // Wt: [64][68]  (W^T: Wt[n][c])
#define SM_A (64 * STRIDE)           // A:  [128][68] (gathered feats, tf32)
#define SM_C (SM_A + 128 * STRIDE)   // C:  [128][68] (fp32 result)
#define SM_FLOATS (SM_C + 128 * STRIDE)
#define SM_BYTES (SM_FLOATS * 4)     // 87,040 B

static __device__ __forceinline__ uint32_t f2tf32(float f) {
    uint32_t r;
    asm("cvt.rna.tf32.f32 %0, %1;" : "=r"(r) : "f"(f));
    return r;
}

static __device__ __forceinline__ void mma_tf32(
    float* c, const uint32_t* a, const uint32_t* b)
{
    asm volatile(
        "mma.sync.aligned.m16n8k8.row.col.f32.tf32.tf32.f32 "
        "{%0,%1,%2,%3}, {%4,%5,%6,%7}, {%8,%9}, {%0,%1,%2,%3};"
        : "+f"(c[0]), "+f"(c[1]), "+f"(c[2]), "+f"(c[3])
        : "r"(a[0]), "r"(a[1]), "r"(a[2]), "r"(a[3]), "r"(b[0]), "r"(b[1]));
}

// ---------------------------------------------------------------------------
__global__ void __launch_bounds__(256) zero_kernel(float4* __restrict__ out, int n4) {
    int i = blockIdx.x * blockDim.x + threadIdx.x;
    if (i < n4) out[i] = make_float4(0.f, 0.f, 0.f, 0.f);
}

// ---------------------------------------------------------------------------
// Persistent gather - tf32 MMA - scatter kernel. 256 threads (8 warps).
// Tile = (k, chunk of 128 pairs). Warp (w&3, w>>2) owns a 32x32 output block.
// ---------------------------------------------------------------------------
__global__ void __launch_bounds__(256, 2) spconv_mma_kernel(
    const float* __restrict__ feats,
    const float* __restrict__ W,
    const int*   __restrict__ in_idx,
    const int*   __restrict__ out_idx,
    float*       __restrict__ out,
    int M, int chunks_per_k, int total_tiles, int tiles_per_cta)
{
    extern __shared__ float sm[];
    float* Wt = sm + SM_W;
    float* A  = sm + SM_A;
    float* C  = sm + SM_C;

    const int tid  = threadIdx.x;
    const int w    = tid >> 5;
    const int lane = tid & 31;
    const int g    = lane >> 2;      // groupID
    const int tg   = lane & 3;       // threadID_in_group
    const int mrow = (w & 3) * 32;   // warp's output row block
    const int ncol = (w >> 2) * 32;  // warp's output col block

    const float4* feats4 = (const float4*)feats;

    const int start = blockIdx.x * tiles_per_cta;
    const int end   = min(total_tiles, start + tiles_per_cta);

    uint32_t b[8][4][2];             // B fragments, register-resident per k
    int curk = -1;

    for (int t = start; t < end; t++) {
        const int k     = t / chunks_per_k;
        const int chunk = t - k * chunks_per_k;
        const int base  = chunk * TILE_M;

        // ---- k changed: stage W^T (tf32) in smem, reload B fragments ----
        if (k != curk) {
            curk = k;
            __syncthreads();
            const float* Wk = W + (size_t)k * CIN * COUT;   // Wk[c][n]
            #pragma unroll 4
            for (int i = tid; i < CIN * COUT; i += 256) {
                int c = i >> 6, n = i & 63;
                ((uint32_t*)Wt)[n * STRIDE + c] = f2tf32(Wk[i]);
            }
            __syncthreads();
            // b0[kk][nb] = Wt[ncol + nb*8 + g][kk*8 + tg], b1: +4 in c
            const uint32_t* pB = (const uint32_t*)Wt + (ncol + g) * STRIDE + tg;
            #pragma unroll
            for (int kk = 0; kk < 8; kk++)
                #pragma unroll
                for (int nb = 0; nb < 4; nb++) {
                    b[kk][nb][0] = pB[nb * 8 * STRIDE + kk * 8];
                    b[kk][nb][1] = pB[nb * 8 * STRIDE + kk * 8 + 4];
                }
        }

        // ---- Gather: warp w loads rows [16w, 16w+16), 16 lanes per row ----
        const int* inK = in_idx + (size_t)k * M;
        {
            const int c4 = lane & 15;
            #pragma unroll
            for (int r = 0; r < 8; r++) {
                int row = 16 * w + 2 * r + (lane >> 4);
                int gp  = base + row;
                int idx = inK[min(gp, M - 1)];
                float4 v = feats4[(size_t)idx * (CIN / 4) + c4];
                uint4 tv;
                tv.x = f2tf32(v.x); tv.y = f2tf32(v.y);
                tv.z = f2tf32(v.z); tv.w = f2tf32(v.w);
                *(uint4*)&A[row * STRIDE + c4 * 4] = *(uint4*)&tv;
            }
        }
        __syncthreads();

        // ---- MMA: 32x32 per warp = 2 m-tiles x 4 n-tiles x 8 k-steps ----
        float acc[2][4][4];
        #pragma unroll
        for (int mt = 0; mt < 2; mt++)
            #pragma unroll
            for (int nt = 0; nt < 4; nt++)
                #pragma unroll
                for (int e = 0; e < 4; e++) acc[mt][nt][e] = 0.f;

        const uint32_t* pA = (const uint32_t*)A + (mrow + g) * STRIDE + tg;
        #pragma unroll
        for (int kk = 0; kk < 8; kk++) {
            uint32_t a[2][4];
            #pragma unroll
            for (int mt = 0; mt < 2; mt++) {
                const uint32_t* q = pA + mt * 16 * STRIDE + kk * 8;
                a[mt][0] = q[0];
                a[mt][1] = q[8 * STRIDE];
                a[mt][2] = q[4];
                a[mt][3] = q[8 * STRIDE + 4];
            }
            #pragma unroll
            for (int mt = 0; mt < 2; mt++)
                #pragma unroll
                for (int nt = 0; nt < 4; nt++)
                    mma_tf32(acc[mt][nt], a[mt], b[kk][nt]);
        }

        // ---- Store C to smem (row-major) for vectorized scatter ----
        #pragma unroll
        for (int mt = 0; mt < 2; mt++)
            #pragma unroll
            for (int nt = 0; nt < 4; nt++) {
                int r0 = mrow + mt * 16 + g;
                int c0 = ncol + nt * 8 + tg * 2;
                *(float2*)&C[r0 * STRIDE + c0]       = make_float2(acc[mt][nt][0], acc[mt][nt][1]);
                *(float2*)&C[(r0 + 8) * STRIDE + c0] = make_float2(acc[mt][nt][2], acc[mt][nt][3]);
            }
        __syncthreads();

        // ---- Scatter: 2 threads per row, 8 x red.v4 each ----
        {
            int row  = tid >> 1;
            int half = tid & 1;
            int gp   = base + row;
            if (gp < M) {
                int o = out_idx[(size_t)k * M + gp];
                float* dst = out + (size_t)o * COUT + half * 32;
                const float4* src = (const float4*)&C[row * STRIDE + half * 32];
                #pragma unroll
                for (int q = 0; q < 8; q++) {
                    float4 v = src[q];
                    asm volatile("red.global.add.v4.f32 [%0], {%1, %2, %3, %4};"
                        :: "l"(dst + q * 4), "f"(v.x), "f"(v.y), "f"(v.z), "f"(v.w)
                        : "memory");
                }
            }
        }
    }
}

// ---------------------------------------------------------------------------
__global__ void __launch_bounds__(256) bn_relu_kernel(
    float4* __restrict__ out,
    const float* __restrict__ gamma,
    const float* __restrict__ beta,
    const float* __restrict__ rmean,
    const float* __restrict__ rvar,
    int total4)
{
    int i = blockIdx.x * blockDim.x + threadIdx.x;
    if (i >= total4) return;
    int c = (i & (COUT / 4 - 1)) * 4;

    float4 v = out[i];
    float s0 = rsqrtf(rvar[c + 0] + BN_EPS) * gamma[c + 0];
    float s1 = rsqrtf(rvar[c + 1] + BN_EPS) * gamma[c + 1];
    float s2 = rsqrtf(rvar[c + 2] + BN_EPS) * gamma[c + 2];
    float s3 = rsqrtf(rvar[c + 3] + BN_EPS) * gamma[c + 3];

    v.x = fmaxf(fmaf(v.x - rmean[c + 0], s0, beta[c + 0]), 0.f);
    v.y = fmaxf(fmaf(v.y - rmean[c + 1], s1, beta[c + 1]), 0.f);
    v.z = fmaxf(fmaf(v.z - rmean[c + 2], s2, beta[c + 2]), 0.f);
    v.w = fmaxf(fmaf(v.w - rmean[c + 3], s3, beta[c + 3]), 0.f);
    out[i] = v;
}

// ---------------------------------------------------------------------------
extern "C" void kernel_launch(void* const* d_in, const int* in_sizes, int n_in,
                              void* d_out, int out_size)
{
    const float* feats   = (const float*)d_in[0];
    const float* W       = (const float*)d_in[1];
    const float* gamma   = (const float*)d_in[2];
    const float* beta    = (const float*)d_in[3];
    const float* rmean   = (const float*)d_in[4];
    const float* rvar    = (const float*)d_in[5];
    const int*   in_idx  = (const int*)d_in[6];
    const int*   out_idx = (const int*)d_in[7];
    float*       out     = (float*)d_out;

    const int N = in_sizes[0] / CIN;
    const int K = in_sizes[1] / (CIN * COUT);
    const int M = in_sizes[6] / K;

    // 1) zero accumulator
    int n4 = N * COUT / 4;
    zero_kernel<<<(n4 + 255) / 256, 256>>>((float4*)out, n4);

    // 2) tf32 mma gather-GEMM-scatter (persistent, 2 CTAs/SM)
    cudaFuncSetAttribute(spconv_mma_kernel,
                         cudaFuncAttributeMaxDynamicSharedMemorySize, SM_BYTES);
    int chunks_per_k = (M + TILE_M - 1) / TILE_M;
    int total_tiles  = K * chunks_per_k;
    int ncta         = 2 * 148;
    if (ncta > total_tiles) ncta = total_tiles;
    int tiles_per_cta = (total_tiles + ncta - 1) / ncta;
    spconv_mma_kernel<<<ncta, 256, SM_BYTES>>>(feats, W, in_idx, out_idx, out,
                                               M, chunks_per_k, total_tiles, tiles_per_cta);

    // 3) BN + ReLU
    int total4 = N * COUT / 4;
    bn_relu_kernel<<<(total4 + 255) / 256, 256>>>((float4*)out, gamma, beta,
                                                  rmean, rvar, total4);
}